// round 16
// baseline (speedup 1.0000x reference)
#include <cuda_runtime.h>
#include <cuda_fp16.h>
#include <math.h>
#include <cstdint>

// Problem constants
#define B_E 128
#define L_L 256
#define HH  12
#define DH  64
#define DD  768           // H*DH
#define N3  2304          // 3*D
#define MROWS (B_E * L_L) // 32768
#define EPS 1e-5f
#define NEGV -10000.0f
#define QSCALE 0.125f     // DH^-0.5

// -------- scratch (allocation-free: __device__ globals) --------
__device__ float g_qkv[(size_t)MROWS * N3];   // fp16 qkv lives in first half
__device__ float g_att[(size_t)MROWS * DD];   // used as fp16
__device__ float g_out1[(size_t)MROWS * DD];
__device__ __half g_ahi[(size_t)MROWS * DD];
__device__ __half g_whi[(size_t)N3 * DD];

// ============================================================
// helpers
// ============================================================
__device__ __forceinline__ uint32_t pack2h(float a, float b) {
    __half2 t = __floats2half2_rn(a, b);
    return *(uint32_t*)&t;
}
__device__ __forceinline__ uint32_t smem_u32(const void* p) {
    uint32_t a;
    asm("{ .reg .u64 t; cvta.to.shared.u64 t, %1; cvt.u32.u64 %0, t; }"
        : "=r"(a) : "l"(p));
    return a;
}

#define MMA_F16(d, a, b)                                                      \
    asm volatile(                                                             \
        "mma.sync.aligned.m16n8k16.row.col.f32.f16.f16.f32 "                  \
        "{%0,%1,%2,%3}, {%4,%5,%6,%7}, {%8,%9}, {%0,%1,%2,%3};"               \
        : "+f"(d[0]), "+f"(d[1]), "+f"(d[2]), "+f"(d[3])                      \
        : "r"(a[0]), "r"(a[1]), "r"(a[2]), "r"(a[3]), "r"(b[0]), "r"(b[1]))

#define LDSM_X4(r0, r1, r2, r3, addr)                                         \
    asm volatile("ldmatrix.sync.aligned.m8n8.x4.shared.b16 {%0,%1,%2,%3}, [%4];" \
        : "=r"(r0), "=r"(r1), "=r"(r2), "=r"(r3) : "r"(addr))
#define LDSM_X4_T(r0, r1, r2, r3, addr)                                       \
    asm volatile("ldmatrix.sync.aligned.m8n8.x4.trans.shared.b16 {%0,%1,%2,%3}, [%4];" \
        : "=r"(r0), "=r"(r1), "=r"(r2), "=r"(r3) : "r"(addr))
#define CP_ASYNC16(s, g)                                                      \
    asm volatile("cp.async.cg.shared.global [%0], [%1], 16;" :: "r"(s), "l"(g))
#define CP_COMMIT  asm volatile("cp.async.commit_group;" ::: "memory")
#define CP_WAIT0   asm volatile("cp.async.wait_group 0;" ::: "memory")
#define CP_WAIT2   asm volatile("cp.async.wait_group 2;" ::: "memory")

// ============================================================
// fp32 -> fp16 convert
// ============================================================
__global__ void __launch_bounds__(256) cvt_kernel(
    const float* __restrict__ in, __half* __restrict__ out, int n4)
{
    int i = blockIdx.x * blockDim.x + threadIdx.x;
    int stride = gridDim.x * blockDim.x;
    for (; i < n4; i += stride) {
        float4 v = ((const float4*)in)[i];
        ((uint32_t*)out)[2 * i + 0] = pack2h(v.x, v.y);
        ((uint32_t*)out)[2 * i + 1] = pack2h(v.z, v.w);
    }
}

// ============================================================
// Warp-MMA fp16 GEMM: C = ah*bh + bias -> fp16 out (q pre-scaled).
// CTA tile 256x128, 8 warps (4x2), 64x64 warp tiles.
// 4-stage cp.async ring. Halves L2 A-traffic vs 128x128.
// ============================================================
#define BK 32
#define ASTR 40
#define ROWB (ASTR * 2)               // 80 B
#define A_TILE_BYTES (256 * ROWB)     // 20480
#define B_TILE_BYTES (128 * ROWB)     // 10240
#define STAGE_BYTES (A_TILE_BYTES + B_TILE_BYTES)  // 30720
#define NSTAGE 4
#define GEMM_SMEM (NSTAGE * STAGE_BYTES)   // 122880

__device__ __forceinline__ void load_stage_async(
    uint32_t sb, int stage,
    const __half* __restrict__ Ahi, const __half* __restrict__ Whi,
    size_t m0, size_t n0, int k0, int tid)
{
    const uint32_t s0 = sb + stage * STAGE_BYTES;
    // A: 256 rows x 4 segs = 1024 chunks
#pragma unroll
    for (int i = 0; i < 4; i++) {
        const int rem = i * 256 + tid;
        const int row = rem >> 2;
        const int seg = rem & 3;
        CP_ASYNC16(s0 + row * ROWB + seg * 16,
                   Ahi + (m0 + row) * DD + k0 + seg * 8);
    }
    // B: 128 rows x 4 segs = 512 chunks
#pragma unroll
    for (int i = 0; i < 2; i++) {
        const int rem = i * 256 + tid;
        const int row = rem >> 2;
        const int seg = rem & 3;
        CP_ASYNC16(s0 + A_TILE_BYTES + row * ROWB + seg * 16,
                   Whi + (n0 + row) * DD + k0 + seg * 8);
    }
}

__global__ void __launch_bounds__(256, 1) mma_gemm_kernel(
    const __half* __restrict__ Ahi, const __half* __restrict__ Whi,
    const float* __restrict__ bias, __half* __restrict__ Chi)
{
    extern __shared__ char sm[];
    const int tid  = threadIdx.x;
    const int wid  = tid >> 5;
    const int lane = tid & 31;
    const int wm   = wid >> 1;        // 0..3  (64 rows each)
    const int wn   = wid & 1;         // 0..1  (64 cols each)
    const int g    = lane >> 2;
    const int tig  = lane & 3;
    const int grp  = lane >> 3;

    const size_t m0 = (size_t)blockIdx.y * 256;
    const size_t n0 = (size_t)blockIdx.x * 128;
    const uint32_t sb = smem_u32(sm);
    const float scale = (blockIdx.x < 6) ? QSCALE : 1.0f;

    const uint32_t aoff = (uint32_t)((wm * 64 + (grp & 1) * 8 + (lane & 7)) * ROWB
                                     + ((grp >> 1) * 8) * 2);
    const uint32_t boff = (uint32_t)(A_TILE_BYTES
                                     + (wn * 64 + (grp >> 1) * 8 + (lane & 7)) * ROWB
                                     + ((grp & 1) * 8) * 2);

    float acc[4][8][4];
#pragma unroll
    for (int mt = 0; mt < 4; mt++)
#pragma unroll
        for (int nt = 0; nt < 8; nt++)
#pragma unroll
            for (int r = 0; r < 4; r++) acc[mt][nt][r] = 0.f;

    const int NKT = DD / BK;   // 24
    load_stage_async(sb, 0, Ahi, Whi, m0, n0, 0, tid);      CP_COMMIT;
    load_stage_async(sb, 1, Ahi, Whi, m0, n0, BK, tid);     CP_COMMIT;
    load_stage_async(sb, 2, Ahi, Whi, m0, n0, 2 * BK, tid); CP_COMMIT;

    for (int kt = 0; kt < NKT; kt++) {
        CP_WAIT2;
        __syncthreads();
        if (kt + 3 < NKT)
            load_stage_async(sb, (kt + 3) & (NSTAGE - 1),
                             Ahi, Whi, m0, n0, (kt + 3) * BK, tid);
        CP_COMMIT;

        const uint32_t sA_h = sb + (uint32_t)(kt & (NSTAGE - 1)) * STAGE_BYTES;

#pragma unroll
        for (int kk = 0; kk < 2; kk++) {
            const int kb = kk * 32;   // bytes
            uint32_t ah[4][4];
#pragma unroll
            for (int mt = 0; mt < 4; mt++) {
                LDSM_X4(ah[mt][0], ah[mt][1], ah[mt][2], ah[mt][3],
                        sA_h + aoff + mt * 16 * ROWB + kb);
            }
            uint32_t bh[4][4];
#pragma unroll
            for (int ntp = 0; ntp < 4; ntp++) {
                LDSM_X4(bh[ntp][0], bh[ntp][1], bh[ntp][2], bh[ntp][3],
                        sA_h + boff + ntp * 16 * ROWB + kb);
            }
#pragma unroll
            for (int mt = 0; mt < 4; mt++)
#pragma unroll
                for (int ntp = 0; ntp < 4; ntp++) {
                    MMA_F16(acc[mt][2 * ntp],     ah[mt], (&bh[ntp][0]));
                    MMA_F16(acc[mt][2 * ntp + 1], ah[mt], (&bh[ntp][2]));
                }
        }
    }

    // Epilogue: bias, q-scale, fp16 write
#pragma unroll
    for (int mt = 0; mt < 4; mt++) {
        const size_t row = m0 + wm * 64 + mt * 16 + g;
#pragma unroll
        for (int nt = 0; nt < 8; nt++) {
            const size_t col = n0 + wn * 64 + nt * 8 + tig * 2;
            const float b0 = bias[col], b1 = bias[col + 1];
            ((uint32_t*)Chi)[(row * N3 + col) >> 1] =
                pack2h((acc[mt][nt][0] + b0) * scale, (acc[mt][nt][1] + b1) * scale);
            ((uint32_t*)Chi)[((row + 8) * N3 + col) >> 1] =
                pack2h((acc[mt][nt][2] + b0) * scale, (acc[mt][nt][3] + b1) * scale);
        }
    }
}

// ============================================================
// Flash MMA attention, pure fp16 operands (1-term QK, 1-term PV).
// 128 queries/block, 4 warps, 2 CTAs/SM, K/V double-buffered.
// ============================================================
#define QROWB 144                       // 72 halves * 2B
#define ATT_SMEM (18432 + 2 * 36864 + 1024)   // 93184

template<int NKEY>
__device__ __forceinline__ void attn_core(
    const __half* __restrict__ qkv, const int* __restrict__ mask,
    __half* __restrict__ out,
    size_t qtok0, size_t ktok0, size_t ts,
    int mask0, int mstride, int h, char* sm)
{
    const int tid = threadIdx.x, wid = tid >> 5, lane = tid & 31;
    const int g = lane >> 2, tig = lane & 3, grp = lane >> 3;
    const uint32_t sb = smem_u32(sm);
    const uint32_t sQ = sb;
    float* nm = (float*)(sm + 18432 + 2 * 36864);

    // ---- prologue: Q + chunk0 via cp.async ----
#pragma unroll
    for (int it = 0; it < 8; it++) {
        int p = it * 128 + tid;
        int row = p >> 3, seg = p & 7;
        const __half* gp = qkv + (qtok0 + (size_t)row * ts) * N3
                         + (size_t)h * DH + seg * 8;
        CP_ASYNC16(sQ + row * QROWB + seg * 16, gp);
    }
    auto load_chunk = [&](int c) {
        const uint32_t sbase = sb + 18432 + (uint32_t)(c & 1) * 36864;
        const int jb = c * 64;
#pragma unroll
        for (int it = 0; it < 4; it++) {
            int p = it * 128 + tid;
            int tok = p >> 3, seg = p & 7;
            const __half* base = qkv
                + (ktok0 + (size_t)(jb + tok) * ts) * N3 + (size_t)h * DH;
            CP_ASYNC16(sbase + tok * QROWB + seg * 16, base + DD + seg * 8);   // K
            CP_ASYNC16(sbase + 18432 + tok * QROWB + seg * 16,
                       base + 2 * DD + seg * 8);                               // V
        }
    };
    load_chunk(0);
    CP_COMMIT;

    for (int j = tid; j < NKEY; j += 128)
        nm[j] = mask[mask0 + j * mstride] ? NEGV : 0.f;

    const uint32_t qA_off = (uint32_t)((wid * 32 + (grp & 1) * 8 + (lane & 7)) * QROWB
                                       + ((grp >> 1) * 8) * 2);
    const uint32_t kB_off = (uint32_t)(((grp >> 1) * 8 + (lane & 7)) * QROWB
                                       + ((grp & 1) * 8) * 2);
    const uint32_t vB_off = (uint32_t)(((grp & 1) * 8 + (lane & 7)) * QROWB
                                       + ((grp >> 1) * 8) * 2);

    float m_[2][2], l_[2][2], O[2][8][4];
#pragma unroll
    for (int a = 0; a < 2; a++)
#pragma unroll
        for (int b = 0; b < 2; b++) { m_[a][b] = -1e30f; l_[a][b] = 0.f; }
#pragma unroll
    for (int a = 0; a < 2; a++)
#pragma unroll
        for (int b = 0; b < 8; b++)
#pragma unroll
            for (int r = 0; r < 4; r++) O[a][b][r] = 0.f;

    const int NC = NKEY / 64;
    for (int c = 0; c < NC; c++) {
        CP_WAIT0;
        __syncthreads();
        if (c + 1 < NC) { load_chunk(c + 1); CP_COMMIT; }

        const uint32_t sK = sb + 18432 + (uint32_t)(c & 1) * 36864;
        const uint32_t sV = sK + 18432;
        const int jb = c * 64;

        // ---- S = Q K^T ----
        float S[2][8][4];
#pragma unroll
        for (int a = 0; a < 2; a++)
#pragma unroll
            for (int b = 0; b < 8; b++)
#pragma unroll
                for (int r = 0; r < 4; r++) S[a][b][r] = 0.f;

#pragma unroll
        for (int kt = 0; kt < 4; kt++) {
            uint32_t aq[2][4];
#pragma unroll
            for (int mt = 0; mt < 2; mt++) {
                LDSM_X4(aq[mt][0], aq[mt][1], aq[mt][2], aq[mt][3],
                        sQ + qA_off + mt * 16 * QROWB + kt * 32);
            }
#pragma unroll
            for (int ntp = 0; ntp < 4; ntp++) {
                uint32_t kh[4];
                LDSM_X4(kh[0], kh[1], kh[2], kh[3],
                        sK + kB_off + ntp * 16 * QROWB + kt * 32);
#pragma unroll
                for (int mt = 0; mt < 2; mt++) {
                    MMA_F16(S[mt][2 * ntp],     aq[mt], (&kh[0]));
                    MMA_F16(S[mt][2 * ntp + 1], aq[mt], (&kh[2]));
                }
            }
        }

        // ---- mask + online softmax ----
#pragma unroll
        for (int mt = 0; mt < 2; mt++)
#pragma unroll
            for (int rh = 0; rh < 2; rh++) {
                float mx = -1e30f;
#pragma unroll
                for (int nt = 0; nt < 8; nt++) {
                    float v0 = S[mt][nt][rh * 2 + 0] + nm[jb + nt * 8 + 2 * tig];
                    float v1 = S[mt][nt][rh * 2 + 1] + nm[jb + nt * 8 + 2 * tig + 1];
                    S[mt][nt][rh * 2 + 0] = v0;
                    S[mt][nt][rh * 2 + 1] = v1;
                    mx = fmaxf(mx, fmaxf(v0, v1));
                }
                mx = fmaxf(mx, __shfl_xor_sync(0xffffffffu, mx, 1));
                mx = fmaxf(mx, __shfl_xor_sync(0xffffffffu, mx, 2));
                float mnew = fmaxf(m_[mt][rh], mx);
                float corr = __expf(m_[mt][rh] - mnew);
                m_[mt][rh] = mnew;
                float ps = 0.f;
#pragma unroll
                for (int nt = 0; nt < 8; nt++) {
                    float p0 = __expf(S[mt][nt][rh * 2 + 0] - mnew);
                    float p1 = __expf(S[mt][nt][rh * 2 + 1] - mnew);
                    S[mt][nt][rh * 2 + 0] = p0;
                    S[mt][nt][rh * 2 + 1] = p1;
                    ps += p0 + p1;
                }
                ps += __shfl_xor_sync(0xffffffffu, ps, 1);
                ps += __shfl_xor_sync(0xffffffffu, ps, 2);
                l_[mt][rh] = l_[mt][rh] * corr + ps;
#pragma unroll
                for (int nt = 0; nt < 8; nt++) {
                    O[mt][nt][rh * 2 + 0] *= corr;
                    O[mt][nt][rh * 2 + 1] *= corr;
                }
            }

        // ---- O += P V ----
#pragma unroll
        for (int kt = 0; kt < 4; kt++) {
            uint32_t ph[2][4];
#pragma unroll
            for (int mt = 0; mt < 2; mt++) {
                ph[mt][0] = pack2h(S[mt][2 * kt][0],     S[mt][2 * kt][1]);
                ph[mt][1] = pack2h(S[mt][2 * kt][2],     S[mt][2 * kt][3]);
                ph[mt][2] = pack2h(S[mt][2 * kt + 1][0], S[mt][2 * kt + 1][1]);
                ph[mt][3] = pack2h(S[mt][2 * kt + 1][2], S[mt][2 * kt + 1][3]);
            }
#pragma unroll
            for (int ntp = 0; ntp < 4; ntp++) {
                uint32_t vh[4];
                LDSM_X4_T(vh[0], vh[1], vh[2], vh[3],
                          sV + vB_off + kt * 16 * QROWB + ntp * 32);
#pragma unroll
                for (int mt = 0; mt < 2; mt++) {
                    MMA_F16(O[mt][2 * ntp],     ph[mt], (&vh[0]));
                    MMA_F16(O[mt][2 * ntp + 1], ph[mt], (&vh[2]));
                }
            }
        }
    }

    // ---- finalize + write fp16 ----
#pragma unroll
    for (int mt = 0; mt < 2; mt++)
#pragma unroll
        for (int rh = 0; rh < 2; rh++) {
            float inv = 1.f / l_[mt][rh];
            int qr = wid * 32 + mt * 16 + g + rh * 8;
            size_t tok = qtok0 + (size_t)qr * ts;
            __half* op = out + tok * DD + h * DH;
#pragma unroll
            for (int nt = 0; nt < 8; nt++) {
                *(uint32_t*)(op + nt * 8 + 2 * tig) =
                    pack2h(O[mt][nt][rh * 2 + 0] * inv, O[mt][nt][rh * 2 + 1] * inv);
            }
        }
}

__global__ void __launch_bounds__(128, 2) row_attn_mma_kernel(
    const __half* __restrict__ qkv, const int* __restrict__ mask,
    __half* __restrict__ out)
{
    extern __shared__ char sm[];
    const int e = blockIdx.x >> 1, qt = blockIdx.x & 1, h = blockIdx.y;
    attn_core<256>(qkv, mask, out,
                   (size_t)e * L_L + qt * 128, (size_t)e * L_L, 1,
                   e * L_L, 1, h, sm);
}

__global__ void __launch_bounds__(128, 2) col_attn_mma_kernel(
    const __half* __restrict__ qkv, const int* __restrict__ mask,
    __half* __restrict__ out)
{
    extern __shared__ char sm[];
    const int l = blockIdx.x, h = blockIdx.y;
    attn_core<128>(qkv, mask, out,
                   (size_t)l, (size_t)l, L_L,
                   l, L_L, h, sm);
}

// ============================================================
// Fused residual-add + LayerNorm, shuffle reduction (2 barriers).
// b (attention output) is fp16. Optional fp16 convert out.
// ============================================================
__global__ void __launch_bounds__(256) add_ln_kernel(
    const float* __restrict__ a, const __half* __restrict__ b,
    const float* __restrict__ g, const float* __restrict__ beta,
    float* __restrict__ dst, __half* __restrict__ hi)
{
    const int m = blockIdx.x;
    const int t = threadIdx.x;
    const int lane = t & 31, wid = t >> 5;
    __shared__ float red[8], red2[8], bc[2];

    float v[3];
    float s = 0.f, sq = 0.f;
#pragma unroll
    for (int r = 0; r < 3; r++) {
        int idx = t + r * 256;
        v[r] = a[(size_t)m * DD + idx] + __half2float(b[(size_t)m * DD + idx]);
        s += v[r];
        sq += v[r] * v[r];
    }
#pragma unroll
    for (int o = 16; o > 0; o >>= 1) {
        s  += __shfl_xor_sync(0xffffffffu, s, o);
        sq += __shfl_xor_sync(0xffffffffu, sq, o);
    }
    if (lane == 0) { red[wid] = s; red2[wid] = sq; }
    __syncthreads();
    if (wid == 0) {
        float ws = (lane < 8) ? red[lane]  : 0.f;
        float wq = (lane < 8) ? red2[lane] : 0.f;
#pragma unroll
        for (int o = 4; o > 0; o >>= 1) {
            ws += __shfl_xor_sync(0xffffffffu, ws, o);
            wq += __shfl_xor_sync(0xffffffffu, wq, o);
        }
        if (lane == 0) { bc[0] = ws * (1.f / DD); bc[1] = wq * (1.f / DD); }
    }
    __syncthreads();
    const float mu   = bc[0];
    const float rstd = rsqrtf(bc[1] - mu * mu + EPS);

#pragma unroll
    for (int r = 0; r < 3; r++) {
        int idx = t + r * 256;
        float y = (v[r] - mu) * rstd * g[idx] + beta[idx];
        dst[(size_t)m * DD + idx] = y;
        if (hi) hi[(size_t)m * DD + idx] = __float2half_rn(y);
    }
}

// ============================================================
// Launch
// ============================================================
extern "C" void kernel_launch(void* const* d_in, const int* in_sizes, int n_in,
                              void* d_out, int out_size)
{
    const float* x     = (const float*)d_in[0];
    const float* w_row = (const float*)d_in[1];
    const float* b_row = (const float*)d_in[2];
    const float* w_col = (const float*)d_in[3];
    const float* b_col = (const float*)d_in[4];
    const float* g1    = (const float*)d_in[5];
    const float* beta1 = (const float*)d_in[6];
    const float* g2    = (const float*)d_in[7];
    const float* beta2 = (const float*)d_in[8];
    const int*   mask  = (const int*)d_in[9];
    float* out = (float*)d_out;

    float *qkvf, *attf, *out1;
    __half *ahi, *whi;
    cudaGetSymbolAddress((void**)&qkvf, g_qkv);
    cudaGetSymbolAddress((void**)&attf, g_att);
    cudaGetSymbolAddress((void**)&out1, g_out1);
    cudaGetSymbolAddress((void**)&ahi,  g_ahi);
    cudaGetSymbolAddress((void**)&whi,  g_whi);
    __half* qh  = (__half*)qkvf;
    __half* att = (__half*)attf;

    cudaFuncSetAttribute(mma_gemm_kernel,
                         cudaFuncAttributeMaxDynamicSharedMemorySize, GEMM_SMEM);
    cudaFuncSetAttribute(row_attn_mma_kernel,
                         cudaFuncAttributeMaxDynamicSharedMemorySize, ATT_SMEM);
    cudaFuncSetAttribute(col_attn_mma_kernel,
                         cudaFuncAttributeMaxDynamicSharedMemorySize, ATT_SMEM);

    const int nA4 = MROWS * DD / 4;
    const int nW4 = N3 * DD / 4;
    dim3 tcg(N3 / 128, MROWS / 256);   // (18, 128)

    // ---- stage 1: row attention ----
    cvt_kernel<<<4096, 256>>>(x, ahi, nA4);
    cvt_kernel<<<1024, 256>>>(w_row, whi, nW4);
    mma_gemm_kernel<<<tcg, 256, GEMM_SMEM>>>(ahi, whi, b_row, qh);
    row_attn_mma_kernel<<<dim3(256, HH), 128, ATT_SMEM>>>(qh, mask, att);
    add_ln_kernel<<<MROWS, 256>>>(x, att, g1, beta1, out1, ahi);

    // ---- stage 2: column attention ----
    cvt_kernel<<<1024, 256>>>(w_col, whi, nW4);
    mma_gemm_kernel<<<tcg, 256, GEMM_SMEM>>>(ahi, whi, b_col, qh);
    col_attn_mma_kernel<<<dim3(L_L, HH), 128, ATT_SMEM>>>(qh, mask, att);
    add_ln_kernel<<<MROWS, 256>>>(out1, att, g2, beta2, out, (__half*)nullptr);
}